// round 1
// baseline (speedup 1.0000x reference)
#include <cuda_runtime.h>
#include <cuda_bf16.h>

#define FULL 0xFFFFFFFFu

// Fused per-(layer,qubit) SU(2) gate U = Rz*Ry*Rx: store u00, u01 (complex).
// u11 = conj(u00), u10 = -conj(u01).
__device__ float4 g_gate[32];

__global__ void prep_gates(const float* __restrict__ w) {
    int g = threadIdx.x;
    if (g >= 32) return;
    int base = g * 3;
    float ta = w[base]     * 0.5f;
    float tb = w[base + 1] * 0.5f;
    float tc = w[base + 2] * 0.5f;
    float sa = sinf(ta), ca = cosf(ta);
    float sb = sinf(tb), cb = cosf(tb);
    float sc = sinf(tc), cc = cosf(tc);
    // M = Ry*Rx: m00 = cb*ca + i sb*sa ; m01 = -sb*ca - i cb*sa
    float m00r = cb * ca, m00i = sb * sa;
    float m01r = -sb * ca, m01i = -cb * sa;
    // u0j = (cc - i sc) * m0j   (Rz row 0)
    float4 u;
    u.x = cc * m00r + sc * m00i;   // u00r
    u.y = cc * m00i - sc * m00r;   // u00i
    u.z = cc * m01r + sc * m01i;   // u01r
    u.w = cc * m01i - sc * m01r;   // u01i
    g_gate[g] = u;
}

// Apply gate G with compile-time slot-pair mask M and role-parity row R.
// Slot s = lane*8 + k. Partner slot = s ^ M. Role bit = parity(R & s).
template<int M, int R, int G>
__device__ __forceinline__ void gate(float (&ar)[8], float (&ai)[8], int lane) {
    const float4 u = g_gate[G];
    constexpr int ML = (M >> 3) & 31;   // lane part of pair mask
    constexpr int MK = M & 7;           // local part
    constexpr int RL = (R >> 3) & 31;   // lane part of parity row
    constexpr int RK = R & 7;           // local part

    int pl = __popc(lane & RL) & 1;
    // SU(2): role flip == sign flip on u00i and u01r only.
    float Ap = pl ? -u.y : u.y;
    float Bp = pl ? -u.z : u.z;

    float br[8], bi[8];
#pragma unroll
    for (int k = 0; k < 8; k++) {
        if (ML) {
            br[k] = __shfl_xor_sync(FULL, ar[k ^ MK], ML);
            bi[k] = __shfl_xor_sync(FULL, ai[k ^ MK], ML);
        } else {
            br[k] = ar[k ^ MK];
            bi[k] = ai[k ^ MK];
        }
    }
    float nr[8], ni[8];
#pragma unroll
    for (int k = 0; k < 8; k++) {
        // parity of (RK & k), k compile-time after unroll -> constant negation
        const bool odd = ((0x96 >> (RK & k)) & 1) != 0;
        float A = odd ? -Ap : Ap;
        float B = odd ? -Bp : Bp;
        nr[k] = u.x * ar[k] - A * ai[k] + B * br[k] - u.w * bi[k];
        ni[k] = u.x * ai[k] + A * ar[k] + B * bi[k] + u.w * br[k];
    }
#pragma unroll
    for (int k = 0; k < 8; k++) { ar[k] = nr[k]; ai[k] = ni[k]; }
}

__global__ void __launch_bounds__(256)
qsim(const float* __restrict__ x, float* __restrict__ out, int B) {
    int warp = (blockIdx.x * blockDim.x + threadIdx.x) >> 5;
    int lane = threadIdx.x & 31;
    if (warp >= B) return;

    // ---- encoding layer: product state, computed directly ----
    float xq = x[warp * 8 + (lane & 7)];
    float sh, ch;
    __sincosf(0.5f * xq, &sh, &ch);
    float c[8], s[8];
#pragma unroll
    for (int q = 0; q < 8; q++) {
        c[q] = __shfl_sync(FULL, ch, q);
        s[q] = __shfl_sync(FULL, sh, q);
    }
    // qubit q <-> state bit (7-q); lane holds bits 7..3, local k holds bits 2..0
    float lp = 1.f;
#pragma unroll
    for (int q = 0; q < 5; q++)
        lp *= ((lane >> (4 - q)) & 1) ? s[q] : c[q];

    float ar[8], ai[8];
#pragma unroll
    for (int k = 0; k < 8; k++) {
        float f = (((k >> 2) & 1) ? s[5] : c[5]) *
                  (((k >> 1) & 1) ? s[6] : c[6]) *
                  (((k)      & 1) ? s[7] : c[7]);
        ar[k] = lp * f;
        ai[k] = 0.f;
    }

    // ---- layer 1 (identity relabeling) ----
    gate<0x80, 0x80,  0>(ar, ai, lane);
    gate<0x40, 0x40,  1>(ar, ai, lane);
    gate<0x20, 0x20,  2>(ar, ai, lane);
    gate<0x10, 0x10,  3>(ar, ai, lane);
    gate<0x08, 0x08,  4>(ar, ai, lane);
    gate<0x04, 0x04,  5>(ar, ai, lane);
    gate<0x02, 0x02,  6>(ar, ai, lane);
    gate<0x01, 0x01,  7>(ar, ai, lane);
    // ---- layer 2 (after CNOT block 1, folded into masks/rows) ----
    gate<0xC0, 0x80,  8>(ar, ai, lane);
    gate<0x60, 0xC0,  9>(ar, ai, lane);
    gate<0x30, 0xE0, 10>(ar, ai, lane);
    gate<0x18, 0xF0, 11>(ar, ai, lane);
    gate<0x0C, 0xF8, 12>(ar, ai, lane);
    gate<0x06, 0xFC, 13>(ar, ai, lane);
    gate<0x03, 0xFE, 14>(ar, ai, lane);
    gate<0x01, 0xFF, 15>(ar, ai, lane);
    // ---- layer 3 ----
    gate<0xA0, 0x80, 16>(ar, ai, lane);
    gate<0x50, 0x40, 17>(ar, ai, lane);
    gate<0x28, 0xA0, 18>(ar, ai, lane);
    gate<0x14, 0x50, 19>(ar, ai, lane);
    gate<0x0A, 0xA8, 20>(ar, ai, lane);
    gate<0x05, 0x54, 21>(ar, ai, lane);
    gate<0x02, 0xAA, 22>(ar, ai, lane);
    gate<0x01, 0x55, 23>(ar, ai, lane);
    // ---- layer 4 ----
    gate<0xF0, 0x80, 24>(ar, ai, lane);
    gate<0x78, 0xC0, 25>(ar, ai, lane);
    gate<0x3C, 0x60, 26>(ar, ai, lane);
    gate<0x1E, 0x30, 27>(ar, ai, lane);
    gate<0x0F, 0x98, 28>(ar, ai, lane);
    gate<0x07, 0xCC, 29>(ar, ai, lane);
    gate<0x03, 0x66, 30>(ar, ai, lane);
    gate<0x01, 0x33, 31>(ar, ai, lane);

    // ---- measurement: <Z_q> with final relabeling rows
    // rows: q0:0x80 q1:0x40 q2:0x20 q3:0x10 q4:0x88 q5:0x44 q6:0x22 q7:0x11
    float P = 0.f, D2 = 0.f, D1 = 0.f, D0 = 0.f;
#pragma unroll
    for (int k = 0; k < 8; k++) {
        float p = ar[k] * ar[k] + ai[k] * ai[k];
        P += p;
        D2 += (k & 4) ? -p : p;
        D1 += (k & 2) ? -p : p;
        D0 += (k & 1) ? -p : p;
    }
    float z[8];
    z[0] = (lane & 16) ? -P : P;
    z[1] = (lane & 8)  ? -P : P;
    z[2] = (lane & 4)  ? -P : P;
    z[3] = (lane & 2)  ? -P : P;
    z[4] = (__popc(lane & 0x11) & 1) ? -P : P;
    z[5] = (lane & 8)  ? -D2 : D2;
    z[6] = (lane & 4)  ? -D1 : D1;
    z[7] = (lane & 2)  ? -D0 : D0;

#pragma unroll
    for (int off = 16; off >= 1; off >>= 1) {
#pragma unroll
        for (int i = 0; i < 8; i++)
            z[i] += __shfl_xor_sync(FULL, z[i], off);
    }
    if (lane == 0) {
        float4* o = (float4*)(out + warp * 8);
        o[0] = make_float4(z[0], z[1], z[2], z[3]);
        o[1] = make_float4(z[4], z[5], z[6], z[7]);
    }
}

extern "C" void kernel_launch(void* const* d_in, const int* in_sizes, int n_in,
                              void* d_out, int out_size) {
    const float* x = (const float*)d_in[0];
    const float* w = (const float*)d_in[1];
    float* out = (float*)d_out;
    int B = in_sizes[0] / 8;

    prep_gates<<<1, 32>>>(w);

    int threads = 256;
    long long total = (long long)B * 32;
    int blocks = (int)((total + threads - 1) / threads);
    qsim<<<blocks, threads>>>(x, out, B);
}